// round 14
// baseline (speedup 1.0000x reference)
#include <cuda_runtime.h>
#include <math.h>

#define H_ 224
#define W_ 224
#define HW 50176
#define NF 4
#define NSAMP 4096
#define EPSF 1e-6f
#define NBLK 296                // 2 blocks/SM x 148 SMs, all co-resident (gsync-safe)
#define NTHR 512
#define FBLK 74                 // blocks per frame in kernel A
#define FSTRIDE (FBLK * NTHR)   // 37888

// ---------------- device scratch (static zero-init; kC tail re-zeros) ----------------
__device__ float    g_mask_frame[NF];
__device__ double   g_sum_absdiff;
__device__ double   g_sum_normal;
__device__ double   g_pose_loss;
__device__ float    g_relgt[NF][12];
__device__ unsigned g_medkeys[NF * HW];
__device__ unsigned g_maskbits[NF * HW / 32];
__device__ unsigned g_h0[NF][2048];
__device__ unsigned g_h1[NF][2][2048];
__device__ unsigned g_h2[NF][2][1024];
__device__ unsigned g_sh0[NF][2048];
__device__ unsigned g_sh1[NF][1024];
__device__ int      g_selcount[NF];
__device__ float4   g_ps[NF][NSAMP];   // pred xyz + 0.5*|p|^2
__device__ float4   g_gs[NF][NSAMP];   // gt   xyz + 0.5*|g|^2
__device__ float    g_w[NF][NSAMP];
__device__ unsigned g_rowmax[2][NF][NSAMP]; // enc = ~f2key(minval); atomicMax; identity 0
__device__ float    g_cd[8];
__device__ float    g_wl[NF];
__device__ unsigned g_done;

// grid barrier (monotonic across replays)
__device__ unsigned          g_cnt;
__device__ volatile unsigned g_gen;

__device__ __forceinline__ void gsync() {
    __syncthreads();
    if (threadIdx.x == 0) {
        unsigned gen = g_gen;
        __threadfence();
        if (atomicAdd(&g_cnt, 1u) == NBLK - 1u) {
            atomicExch(&g_cnt, 0u);
            __threadfence();
            g_gen = gen + 1u;
        } else {
            while (g_gen == gen) { }
        }
        __threadfence();
    }
    __syncthreads();
}

// ---------------- helpers ----------------
__device__ __forceinline__ float blockReduceSum(float v, float* sh) {
    int lane = threadIdx.x & 31, wid = threadIdx.x >> 5;
#pragma unroll
    for (int o = 16; o; o >>= 1) v += __shfl_down_sync(0xffffffffu, v, o);
    if (lane == 0) sh[wid] = v;
    __syncthreads();
    int nw = (int)(blockDim.x + 31) >> 5;
    v = (threadIdx.x < nw) ? sh[threadIdx.x] : 0.f;
    if (wid == 0) {
#pragma unroll
        for (int o = 16; o; o >>= 1) v += __shfl_down_sync(0xffffffffu, v, o);
    }
    return v;
}

// 512 threads; thread t owns bins 4t..4t+3. total + exclusive prefix before bin 4t.
__device__ __forceinline__ unsigned blockScan4(const unsigned* a, unsigned* ws, unsigned& excl) {
    __syncthreads();
    unsigned lane = threadIdx.x & 31, wid = threadIdx.x >> 5;
    unsigned s = a[0] + a[1] + a[2] + a[3];
    unsigned v = s;
#pragma unroll
    for (int o = 1; o < 32; o <<= 1) { unsigned t = __shfl_up_sync(0xffffffffu, v, o); if (lane >= o) v += t; }
    if (lane == 31) ws[wid] = v;
    __syncthreads();
    if (wid == 0) {
        unsigned w = (lane < 16) ? ws[lane] : 0u;
#pragma unroll
        for (int o = 1; o < 32; o <<= 1) { unsigned t = __shfl_up_sync(0xffffffffu, w, o); if (lane >= o) w += t; }
        ws[lane] = w;
    }
    __syncthreads();
    unsigned warpoff = wid ? ws[wid - 1] : 0u;
    excl = warpoff + v - s;
    return ws[15];
}

__device__ __forceinline__ unsigned f2key(float v) {
    unsigned b = __float_as_uint(v);
    return (b & 0x80000000u) ? ~b : (b | 0x80000000u);
}
__device__ __forceinline__ float key2f(unsigned k) {
    unsigned b = (k & 0x80000000u) ? (k ^ 0x80000000u) : ~k;
    return __uint_as_float(b);
}

__device__ __forceinline__ unsigned long long pk2(float lo, float hi) {
    unsigned long long u;
    asm("mov.b64 %0,{%1,%2};" : "=l"(u) : "f"(lo), "f"(hi));
    return u;
}
__device__ __forceinline__ void upk2(unsigned long long u, float& lo, float& hi) {
    asm("mov.b64 {%0,%1},%2;" : "=f"(lo), "=f"(hi) : "l"(u));
}
__device__ __forceinline__ unsigned long long fma2(unsigned long long a,
                                                   unsigned long long b,
                                                   unsigned long long c) {
    unsigned long long d;
    asm("fma.rn.f32x2 %0,%1,%2,%3;" : "=l"(d) : "l"(a), "l"(b), "l"(c));
    return d;
}

__device__ void inv4(const float* m, float* inv) {
    float s0 = m[0] * m[5] - m[4] * m[1];
    float s1 = m[0] * m[6] - m[4] * m[2];
    float s2 = m[0] * m[7] - m[4] * m[3];
    float s3 = m[1] * m[6] - m[5] * m[2];
    float s4 = m[1] * m[7] - m[5] * m[3];
    float s5 = m[2] * m[7] - m[6] * m[3];
    float c5 = m[10] * m[15] - m[14] * m[11];
    float c4 = m[9] * m[15] - m[13] * m[11];
    float c3 = m[9] * m[14] - m[13] * m[10];
    float c2 = m[8] * m[15] - m[12] * m[11];
    float c1 = m[8] * m[14] - m[12] * m[10];
    float c0 = m[8] * m[13] - m[12] * m[9];
    float det = s0 * c5 - s1 * c4 + s2 * c3 + s3 * c2 - s4 * c1 + s5 * c0;
    float id = 1.f / det;
    inv[0]  = ( m[5] * c5 - m[6] * c4 + m[7] * c3) * id;
    inv[1]  = (-m[1] * c5 + m[2] * c4 - m[3] * c3) * id;
    inv[2]  = ( m[13] * s5 - m[14] * s4 + m[15] * s3) * id;
    inv[3]  = (-m[9] * s5 + m[10] * s4 - m[11] * s3) * id;
    inv[4]  = (-m[4] * c5 + m[6] * c2 - m[7] * c1) * id;
    inv[5]  = ( m[0] * c5 - m[2] * c2 + m[3] * c1) * id;
    inv[6]  = (-m[12] * s5 + m[14] * s2 - m[15] * s1) * id;
    inv[7]  = ( m[8] * s5 - m[10] * s2 + m[11] * s1) * id;
    inv[8]  = ( m[4] * c4 - m[5] * c2 + m[7] * c0) * id;
    inv[9]  = (-m[0] * c4 + m[1] * c2 - m[3] * c0) * id;
    inv[10] = ( m[12] * s4 - m[13] * s2 + m[15] * s0) * id;
    inv[11] = (-m[8] * s4 + m[9] * s2 - m[11] * s0) * id;
    inv[12] = (-m[4] * c3 + m[5] * c1 - m[6] * c0) * id;
    inv[13] = ( m[0] * c3 - m[1] * c1 + m[2] * c0) * id;
    inv[14] = (-m[12] * s3 + m[13] * s1 - m[14] * s0) * id;
    inv[15] = ( m[8] * s3 - m[9] * s1 + m[10] * s0) * id;
}

__device__ void mm4(const float* A, const float* B, float* C) {
    for (int i = 0; i < 4; i++)
        for (int j = 0; j < 4; j++) {
            float s = 0.f;
            for (int k = 0; k < 4; k++) s += A[i * 4 + k] * B[k * 4 + j];
            C[i * 4 + j] = s;
        }
}

__device__ __forceinline__ void compnorm(int x, int y,
                                         float dL, float dR, float dU, float dD,
                                         float cx, float cy, float ifx, float ify,
                                         float* out) {
    float Rx = ((float)(x + 1) - cx) * ifx * dR, Ry = ((float)y - cy) * ify * dR, Rz = dR;
    float Lx = ((float)(x - 1) - cx) * ifx * dL, Ly = ((float)y - cy) * ify * dL, Lz = dL;
    float Dx = ((float)x - cx) * ifx * dD, Dy = ((float)(y + 1) - cy) * ify * dD, Dz = dD;
    float Ux = ((float)x - cx) * ifx * dU, Uy = ((float)(y - 1) - cy) * ify * dU, Uz = dU;
    float bx = Rx - Lx, by = Ry - Ly, bz = Rz - Lz;
    float ax = Dx - Ux, ay = Dy - Uy, az = Dz - Uz;
    float c0 = ay * bz - az * by;
    float c1 = az * bx - ax * bz;
    float c2 = ax * by - ay * bx;
    float n = sqrtf(c0 * c0 + c1 * c1 + c2 * c2);
    float iv = 1.f / fmaxf(n, EPSF);
    out[0] = c0 * iv; out[1] = c1 * iv; out[2] = c2 * iv;
}

// ================= kernel A: selection pipeline + per-pixel losses + gather =================
// 296 blocks, 2/SM guaranteed by launch_bounds(512,2) -> all co-resident, gsync safe.
__global__ void __launch_bounds__(NTHR, 2) kA(
    const float* __restrict__ dp, const float* __restrict__ ppts,
    const float* __restrict__ dg, const float* __restrict__ intr,
    const float* __restrict__ posep, const float* __restrict__ poseg) {
    __shared__ unsigned sh[2048];
    __shared__ unsigned ws[32];
    __shared__ float shf[32];
    __shared__ unsigned s_p0[2], s_r1[2], s_p1[2], s_r2[2];
    __shared__ unsigned s_selbin, s_selneed, s_selT;
    __shared__ int s_low;
    __shared__ float s_sval[2], s_scale;
    __shared__ unsigned s_wcnt[16];
    __shared__ int s_base;

    const int bid = blockIdx.x, tix = threadIdx.x;
    const int f = bid & 3, cb = bid >> 2;   // cb in 0..73
    const float* dpf = dp + (size_t)f * HW;
    const float* dgf = dg + (size_t)f * HW;

    if (bid == NBLK - 1 && tix == 0) {
        float ip[16], ig[16];
        inv4(posep, ip);
        inv4(poseg, ig);
        float acc = 0.f;
        for (int s = 0; s < NF; s++) {
            float rp[16], rg[16];
            mm4(ip, posep + s * 16, rp);
            mm4(ig, poseg + s * 16, rg);
            for (int k = 0; k < 16; k++) acc += fabsf(rp[k] - rg[k]);
            g_relgt[s][0] = rg[0];  g_relgt[s][1] = rg[1];  g_relgt[s][2] = rg[2];
            g_relgt[s][3] = rg[4];  g_relgt[s][4] = rg[5];  g_relgt[s][5] = rg[6];
            g_relgt[s][6] = rg[8];  g_relgt[s][7] = rg[9];  g_relgt[s][8] = rg[10];
            g_relgt[s][9] = rg[3];  g_relgt[s][10] = rg[7]; g_relgt[s][11] = rg[11];
        }
        g_pose_loss = (double)(acc / 64.f);
    }

    // ---------- P1: keys, L0 hists, mask bits ----------
    for (int i = tix; i < 2048; i += NTHR) sh[i] = 0;
    __syncthreads();
    for (int pi = cb * NTHR + tix; pi < HW; pi += FSTRIDE) {
        float dgv = dgf[pi], dpv = dpf[pi];
        bool mk = (dgv > 0.f) && isfinite(dgv) && (dgv > 1e-6f);
        bool mm = mk && isfinite(dpv) && (dpv > 1e-6f);
        unsigned key = 0u;
        if (mm) {
            float r = dpv / fmaxf(dgv, EPSF);
            key = f2key(r);
            if (!key) key = 1u;
        }
        g_medkeys[f * HW + pi] = key;
        if (key) atomicAdd(&sh[key >> 21], 1u);
        unsigned bal = __ballot_sync(0xffffffffu, mk);
        if ((pi & 31) == 0) g_maskbits[(f * HW + pi) >> 5] = bal;
        unsigned sk = (((unsigned)pi * 2654435761u) & 0xFFFFFu) | (mk ? (1u << 20) : 0u);
        atomicAdd(&g_sh0[f][sk >> 10], 1u);
    }
    __syncthreads();
    for (int i = tix; i < 2048; i += NTHR) {
        unsigned v = sh[i];
        if (v) atomicAdd(&g_h0[f][i], v);
    }
    gsync();

    // ---------- P2: local L0 scans + L1 hists ----------
    {
        if (tix == 0) { s_p0[0] = s_p0[1] = 0; s_r1[0] = s_r1[1] = 0; }
        unsigned a[4];
#pragma unroll
        for (int k = 0; k < 4; k++) a[k] = g_h0[f][4 * tix + k];
        unsigned excl;
        unsigned total = blockScan4(a, ws, excl);
        if (tix == 0) s_low = (total < 16) ? 1 : 0;
        if (total) {
            unsigned r0, r1;
            if (total & 1u) { r0 = total >> 1; r1 = r0; }
            else { r0 = (total >> 1) - 1u; r1 = total >> 1; }
            unsigned rks[2] = {r0, r1};
#pragma unroll
            for (int q = 0; q < 2; q++) {
                unsigned rk = rks[q], cum = excl;
#pragma unroll
                for (int k = 0; k < 4; k++) {
                    if (rk >= cum && rk < cum + a[k]) { s_p0[q] = 4 * tix + k; s_r1[q] = rk - cum; }
                    cum += a[k];
                }
            }
        }
        unsigned b4[4];
#pragma unroll
        for (int k = 0; k < 4; k++) b4[k] = g_sh0[f][4 * tix + k];
        unsigned excl2;
        unsigned tot2 = blockScan4(b4, ws, excl2);
        unsigned rk = tot2 - NSAMP, cum = excl2;
#pragma unroll
        for (int k = 0; k < 4; k++) {
            if (rk >= cum && rk < cum + b4[k]) { s_selbin = 4 * tix + k; s_selneed = cum + b4[k] - rk; }
            cum += b4[k];
        }
        __syncthreads();
        unsigned p0 = s_p0[0], p1 = s_p0[1], selbin = s_selbin;
        for (int pi = cb * NTHR + tix; pi < HW; pi += FSTRIDE) {
            unsigned key = g_medkeys[f * HW + pi];
            if (key) {
                unsigned top = key >> 21, mid = (key >> 10) & 2047u;
                if (top == p0) atomicAdd(&g_h1[f][0][mid], 1u);
                if (p1 != p0 && top == p1) atomicAdd(&g_h1[f][1][mid], 1u);
            }
            unsigned mk = (g_maskbits[(f * HW + pi) >> 5] >> (pi & 31)) & 1u;
            unsigned sk = (((unsigned)pi * 2654435761u) & 0xFFFFFu) | (mk << 20);
            if ((sk >> 10) == selbin) atomicAdd(&g_sh1[f][sk & 1023u], 1u);
        }
    }
    gsync();

    // ---------- P3: local L1 scans + L2 hist ----------
    {
        if (tix == 0) { s_p1[0] = s_p1[1] = 0; s_r2[0] = s_r2[1] = 0; }
        bool eq = (s_p0[0] == s_p0[1]);
#pragma unroll
        for (int q = 0; q < 2; q++) {
            int src = (eq && q == 1) ? 0 : q;
            unsigned a[4];
#pragma unroll
            for (int k = 0; k < 4; k++) a[k] = g_h1[f][src][4 * tix + k];
            unsigned excl;
            blockScan4(a, ws, excl);
            unsigned rk = s_r1[q], cum = excl;
#pragma unroll
            for (int k = 0; k < 4; k++) {
                if (rk >= cum && rk < cum + a[k]) {
                    s_p1[q] = (s_p0[q] << 11) | (unsigned)(4 * tix + k);
                    s_r2[q] = rk - cum;
                }
                cum += a[k];
            }
        }
        __syncthreads();
        unsigned q0 = s_p1[0], q1 = s_p1[1];
        for (int pi = cb * NTHR + tix; pi < HW; pi += FSTRIDE) {
            unsigned key = g_medkeys[f * HW + pi];
            if (!key) continue;
            unsigned hi = key >> 10;
            if (hi == q0) atomicAdd(&g_h2[f][0][key & 1023u], 1u);
            if (q1 != q0 && hi == q1) atomicAdd(&g_h2[f][1][key & 1023u], 1u);
        }
    }
    gsync();

    // ---------- P4: L2 scans -> scale; sel L1 scan -> selT; pixel losses; gather ----------
    {
        if (tix < 2) s_sval[tix] = 0.f;
        bool eq = (s_p1[0] == s_p1[1]);
#pragma unroll
        for (int q = 0; q < 2; q++) {
            int src = (eq && q == 1) ? 0 : q;
            unsigned a[4];
#pragma unroll
            for (int k = 0; k < 4; k++) a[k] = (4 * tix + k < 1024) ? g_h2[f][src][4 * tix + k] : 0u;
            unsigned excl;
            blockScan4(a, ws, excl);
            unsigned rk = s_r2[q], cum = excl;
#pragma unroll
            for (int k = 0; k < 4; k++) {
                if (4 * tix + k < 1024 && rk >= cum && rk < cum + a[k])
                    s_sval[q] = key2f((s_p1[q] << 10) | (unsigned)(4 * tix + k));
                cum += a[k];
            }
        }
        {
            unsigned a[4];
#pragma unroll
            for (int k = 0; k < 4; k++) a[k] = (4 * tix + k < 1024) ? g_sh1[f][4 * tix + k] : 0u;
            unsigned excl;
            unsigned tot = blockScan4(a, ws, excl);
            unsigned rk = tot - s_selneed, cum = excl;
#pragma unroll
            for (int k = 0; k < 4; k++) {
                if (4 * tix + k < 1024 && rk >= cum && rk < cum + a[k])
                    s_selT = (s_selbin << 10) | (unsigned)(4 * tix + k);
                cum += a[k];
            }
        }
        __syncthreads();
        if (tix == 0) {
            float med = 0.5f * (s_sval[0] + s_sval[1]);
            s_scale = (s_low || !isfinite(med)) ? 1.f : fminf(fmaxf(med, 1e-3f), 1e3f);
        }
        __syncthreads();

        const float sc = s_scale;
        const unsigned T = s_selT;
        const float fx = fmaxf(intr[f * 9 + 0], EPSF), fy = fmaxf(intr[f * 9 + 4], EPSF);
        const float cx = intr[f * 9 + 2], cy = intr[f * 9 + 5];
        const float ifx = 1.f / fx, ify = 1.f / fy;
        const int lane = tix & 31, wid = tix >> 5;

        // -- losses (gather removed from this loop) --
        float accm = 0.f, accl1 = 0.f, accn = 0.f;
        for (int pi = cb * NTHR + tix; pi < HW; pi += FSTRIDE) {
            int y = pi / W_, x = pi - y * W_;
            float dgv = dgf[pi], dpv = dpf[pi];
            bool mask = (dgv > 0.f) && isfinite(dgv) && (dgv > 1e-6f);
            float mterm = mask ? 1.f : 0.f;
            accm += mterm;
            accl1 += fabsf(dpv - dgv * sc) * mterm;
            float cosv = 0.f;
            if (x > 0 && x < W_ - 1 && y > 0 && y < H_ - 1) {
                float pL = dpf[pi - 1], pR = dpf[pi + 1], pU = dpf[pi - W_], pD = dpf[pi + W_];
                float gL = dgf[pi - 1] * sc, gR = dgf[pi + 1] * sc, gU = dgf[pi - W_] * sc, gD = dgf[pi + W_] * sc;
                float n1[3], n2[3];
                compnorm(x, y, pL, pR, pU, pD, cx, cy, ifx, ify, n1);
                compnorm(x, y, gL, gR, gU, gD, cx, cy, ifx, ify, n2);
                float d = n1[0] * n2[0] + n1[1] * n2[1] + n1[2] * n2[2];
                cosv = fminf(fmaxf(d, -1.f), 1.f);
            }
            accn += (1.f - cosv) * mterm;
        }
        float s;
        s = blockReduceSum(accl1, shf);
        if (tix == 0) atomicAdd(&g_sum_absdiff, (double)s);
        __syncthreads();
        s = blockReduceSum(accn, shf);
        if (tix == 0) atomicAdd(&g_sum_normal, (double)s);
        __syncthreads();
        s = blockReduceSum(accm, shf);
        if (tix == 0 && s != 0.f) atomicAdd(&g_mask_frame[f], s);
        __syncthreads();

        // -- gather with block-aggregated slot allocation (1 global atomic per block) --
        const int pi0 = cb * NTHR + tix;          // always < HW
        const int pi1 = pi0 + FSTRIDE;            // may be >= HW
        float dg0 = dgf[pi0];
        bool mk0 = (dg0 > 0.f) && isfinite(dg0) && (dg0 > 1e-6f);
        bool sel0 = ((((unsigned)pi0 * 2654435761u) & 0xFFFFFu) | (mk0 ? (1u << 20) : 0u)) >= T;
        float dg1 = 0.f;
        bool mk1 = false, sel1 = false;
        if (pi1 < HW) {
            dg1 = dgf[pi1];
            mk1 = (dg1 > 0.f) && isfinite(dg1) && (dg1 > 1e-6f);
            sel1 = ((((unsigned)pi1 * 2654435761u) & 0xFFFFFu) | (mk1 ? (1u << 20) : 0u)) >= T;
        }
        unsigned b0 = __ballot_sync(0xffffffffu, sel0);
        unsigned b1 = __ballot_sync(0xffffffffu, sel1);
        if (lane == 0) s_wcnt[wid] = (unsigned)(__popc(b0) + __popc(b1));
        __syncthreads();
        if (tix < 32) {
            unsigned v = (tix < 16) ? s_wcnt[tix] : 0u;
            unsigned inc = v;
#pragma unroll
            for (int o = 1; o < 16; o <<= 1) { unsigned t = __shfl_up_sync(0xffffffffu, inc, o); if (tix >= o) inc += t; }
            if (tix < 16) s_wcnt[tix] = inc - v;            // exclusive prefix per warp
            if (tix == 15) s_base = atomicAdd(&g_selcount[f], (int)inc);  // inc = block total
        }
        __syncthreads();
        const int wbase = s_base + (int)s_wcnt[wid];
        const float r00 = g_relgt[f][0], r01 = g_relgt[f][1], r02 = g_relgt[f][2];
        const float r10 = g_relgt[f][3], r11 = g_relgt[f][4], r12 = g_relgt[f][5];
        const float r20 = g_relgt[f][6], r21 = g_relgt[f][7], r22 = g_relgt[f][8];
        const float t0 = g_relgt[f][9], t1 = g_relgt[f][10], t2 = g_relgt[f][11];
        const unsigned below = (1u << lane) - 1u;
#pragma unroll
        for (int it = 0; it < 2; it++) {
            bool sel = it ? sel1 : sel0;
            if (!sel) continue;
            int pi = it ? pi1 : pi0;
            float dgv = it ? dg1 : dg0;
            bool mask = it ? mk1 : mk0;
            int slot = wbase + (it ? (__popc(b0) + __popc(b1 & below)) : __popc(b0 & below));
            if (slot < NSAMP) {
                float w = mask ? 1.f : 0.f;
                const float* pp3 = ppts + ((size_t)f * HW + pi) * 3;
                float px = pp3[0], py = pp3[1], pz = pp3[2];
                if (!mask) { px = 1e9f; py = 1e9f; pz = 1e9f; }
                g_ps[f][slot] = make_float4(px, py, pz, 0.5f * (px * px + py * py + pz * pz));
                int y = pi / W_, x = pi - y * W_;
                float dgal = dgv * sc;
                float X = ((float)x - cx) * ifx * dgal;
                float Y = ((float)y - cy) * ify * dgal;
                float Z = dgal;
                float gx = r00 * X + r01 * Y + r02 * Z + t0;
                float gy = r10 * X + r11 * Y + r12 * Z + t1;
                float gz = r20 * X + r21 * Y + r22 * Z + t2;
                if (!mask) { gx = 1e9f; gy = 1e9f; gz = 1e9f; }
                g_gs[f][slot] = make_float4(gx, gy, gz, 0.5f * (gx * gx + gy * gy + gz * gz));
                g_w[f][slot] = w;
            }
        }
    }
}

// ========== kernel B: chamfer, 256 blocks x 512 threads, 2 rows/thread, 512-col tile ==========
__global__ void __launch_bounds__(512, 2) kB() {
    __shared__ ulonglong2 sP[256];
    __shared__ ulonglong2 sQ[256];

    const int bid = blockIdx.x, tix = threadIdx.x;
    const int dir = bid & 1, f = (bid >> 1) & 3, rowblk = (bid >> 3) & 3, colblk = bid >> 5;
    const float4* A = dir ? g_gs[f] : g_ps[f];
    const float4* B = dir ? g_ps[f] : g_gs[f];

    const int cbase = colblk * 512;
    if (tix < 256) {
        float4 c0 = B[cbase + 2 * tix];
        float4 c1 = B[cbase + 2 * tix + 1];
        sP[tix] = make_ulonglong2(pk2(c0.x, c1.x), pk2(c0.y, c1.y));
        sQ[tix] = make_ulonglong2(pk2(c0.z, c1.z), pk2(c0.w, c1.w));
    }
    const int r0 = rowblk * 1024 + tix, r1 = r0 + 512;
    float4 a0 = A[r0], a1 = A[r1];
    unsigned long long nax0 = pk2(-a0.x, -a0.x), nay0 = pk2(-a0.y, -a0.y), naz0 = pk2(-a0.z, -a0.z);
    unsigned long long nax1 = pk2(-a1.x, -a1.x), nay1 = pk2(-a1.y, -a1.y), naz1 = pk2(-a1.z, -a1.z);
    float m0a = 3e38f, m0b = 3e38f, m1a = 3e38f, m1b = 3e38f;
    __syncthreads();
#pragma unroll 8
    for (int j = 0; j < 256; j++) {
        ulonglong2 va = sP[j], vb = sQ[j];
        unsigned long long u0 = fma2(nax0, va.x, vb.y);
        u0 = fma2(nay0, va.y, u0);
        u0 = fma2(naz0, vb.x, u0);
        unsigned long long u1 = fma2(nax1, va.x, vb.y);
        u1 = fma2(nay1, va.y, u1);
        u1 = fma2(naz1, vb.x, u1);
        float e0, e1;
        upk2(u0, e0, e1);
        m0a = fminf(m0a, e0); m0b = fminf(m0b, e1);
        upk2(u1, e0, e1);
        m1a = fminf(m1a, e0); m1b = fminf(m1b, e1);
    }
    atomicMax(&g_rowmax[dir][f][r0], ~f2key(fminf(m0a, m0b)));
    atomicMax(&g_rowmax[dir][f][r1], ~f2key(fminf(m1a, m1b)));
}

// ========== kernel C: per-(dir,frame) reduce + last-block combine + state reset ==========
__global__ void kC(float* out) {
    __shared__ float shf[32];
    __shared__ int s_last;
    const int b = blockIdx.x, tix = threadIdx.x;   // 8 blocks x 512
    const int f = b & 3, dir = b >> 2;
    float acc = 0.f, accw = 0.f;
    for (int i = tix; i < NSAMP; i += 512) {
        float rmin = key2f(~g_rowmax[dir][f][i]);
        float aw = dir ? g_gs[f][i].w : g_ps[f][i].w;
        float w = g_w[f][i];
        float d = fminf(sqrtf(fmaxf(2.f * (rmin + aw), 1e-12f)), 1e9f);
        acc += d * w;
        accw += w;
    }
    float r = blockReduceSum(acc, shf);
    if (tix == 0) g_cd[b] = r;
    __syncthreads();
    float rw = blockReduceSum(accw, shf);
    if (tix == 0 && dir == 0) g_wl[f] = rw;

    for (int i = tix; i < NSAMP; i += 512) g_rowmax[dir][f][i] = 0u;

    {
        const int gs = 8 * 512;
        int g = b * 512 + tix;
        unsigned* h0 = (unsigned*)g_h0;   for (int i = g; i < NF * 2048; i += gs) h0[i] = 0u;
        unsigned* s0 = (unsigned*)g_sh0;  for (int i = g; i < NF * 2048; i += gs) s0[i] = 0u;
        unsigned* h1 = (unsigned*)g_h1;   for (int i = g; i < NF * 2 * 2048; i += gs) h1[i] = 0u;
        unsigned* h2 = (unsigned*)g_h2;   for (int i = g; i < NF * 2 * 1024; i += gs) h2[i] = 0u;
        unsigned* s1 = (unsigned*)g_sh1;  for (int i = g; i < NF * 1024; i += gs) s1[i] = 0u;
    }

    __threadfence();
    __syncthreads();
    if (tix == 0) s_last = (atomicAdd(&g_done, 1u) == 7u) ? 1 : 0;
    __syncthreads();
    if (!s_last) return;

    if (tix == 0) {
        float wsum = g_mask_frame[0] + g_mask_frame[1] + g_mask_frame[2] + g_mask_frame[3];
        float denom = fmaxf(wsum, 1.f);
        float depth_loss = (float)g_sum_absdiff / denom;
        float normal_loss = (float)g_sum_normal / denom;
        float cds = 0.f, oks = 0.f;
        for (int ff = 0; ff < NF; ff++) {
            float dn = fmaxf(g_wl[ff], 1.f);
            if (g_mask_frame[ff] >= 10.f) { cds += (g_cd[ff] + g_cd[4 + ff]) / dn; oks += 1.f; }
        }
        float points_loss = cds / fmaxf(oks, 1.f);
        out[0] = (float)g_pose_loss + depth_loss + points_loss + normal_loss;
    }
    __syncthreads();
    if (tix < NF) { g_mask_frame[tix] = 0.f; g_selcount[tix] = 0; }
    if (tix == NF) { g_sum_absdiff = 0.0; g_sum_normal = 0.0; g_done = 0u; }
}

// ---------------- launcher ----------------
extern "C" void kernel_launch(void* const* d_in, const int* in_sizes, int n_in,
                              void* d_out, int out_size) {
    const float* depth_pred = (const float*)d_in[0];
    const float* points_pred = (const float*)d_in[1];
    const float* depth_gt = (const float*)d_in[2];
    const float* intrinsics = (const float*)d_in[3];
    const float* pose_pred = (const float*)d_in[4];
    const float* pose_gt = (const float*)d_in[5];
    float* out = (float*)d_out;

    kA<<<NBLK, NTHR>>>(depth_pred, points_pred, depth_gt, intrinsics, pose_pred, pose_gt);
    kB<<<256, 512>>>();
    kC<<<8, 512>>>(out);
}

// round 15
// speedup vs baseline: 1.4008x; 1.4008x over previous
#include <cuda_runtime.h>
#include <math.h>

#define H_ 224
#define W_ 224
#define HW 50176
#define NF 4
#define NSAMP 4096
#define EPSF 1e-6f
#define NBLK 296                // 2 blocks/SM x 148 SMs, all co-resident (gsync-safe)
#define NTHR 512
#define FBLK 74                 // blocks per frame in kernel A
#define FSTRIDE (FBLK * NTHR)   // 37888

// ---------------- device scratch (static zero-init; kC tail re-zeros) ----------------
__device__ float    g_mask_frame[NF];
__device__ double   g_sum_absdiff;
__device__ double   g_sum_normal;
__device__ double   g_pose_loss;
__device__ float    g_relgt[NF][12];
__device__ unsigned g_medkeys[NF * HW];
__device__ unsigned g_maskbits[NF * HW / 32];
__device__ unsigned g_h0[NF][2048];
__device__ unsigned g_h1[NF][2][2048];
__device__ unsigned g_h2[NF][2][1024];
__device__ unsigned g_sh0[NF][2048];
__device__ unsigned g_sh1[NF][1024];
__device__ int      g_selcount[NF];
__device__ float4   g_ps[NF][NSAMP];   // pred xyz + 0.5*|p|^2
__device__ float4   g_gs[NF][NSAMP];   // gt   xyz + 0.5*|g|^2
__device__ float    g_w[NF][NSAMP];
__device__ unsigned g_rowmax[2][NF][NSAMP]; // enc = ~f2key(minval); atomicMax; identity 0
__device__ float    g_cd[8];
__device__ float    g_wl[NF];
__device__ unsigned g_done;

// grid barrier (monotonic across replays)
__device__ unsigned          g_cnt;
__device__ volatile unsigned g_gen;

__device__ __forceinline__ void gsync() {
    __syncthreads();
    if (threadIdx.x == 0) {
        unsigned gen = g_gen;
        __threadfence();
        if (atomicAdd(&g_cnt, 1u) == NBLK - 1u) {
            atomicExch(&g_cnt, 0u);
            __threadfence();
            g_gen = gen + 1u;
        } else {
            while (g_gen == gen) { }
        }
        __threadfence();
    }
    __syncthreads();
}

// ---------------- helpers ----------------
__device__ __forceinline__ float blockReduceSum(float v, float* sh) {
    int lane = threadIdx.x & 31, wid = threadIdx.x >> 5;
#pragma unroll
    for (int o = 16; o; o >>= 1) v += __shfl_down_sync(0xffffffffu, v, o);
    if (lane == 0) sh[wid] = v;
    __syncthreads();
    int nw = (int)(blockDim.x + 31) >> 5;
    v = (threadIdx.x < nw) ? sh[threadIdx.x] : 0.f;
    if (wid == 0) {
#pragma unroll
        for (int o = 16; o; o >>= 1) v += __shfl_down_sync(0xffffffffu, v, o);
    }
    return v;
}

// 512 threads; thread t owns bins 4t..4t+3. total + exclusive prefix before bin 4t.
__device__ __forceinline__ unsigned blockScan4(const unsigned* a, unsigned* ws, unsigned& excl) {
    __syncthreads();
    unsigned lane = threadIdx.x & 31, wid = threadIdx.x >> 5;
    unsigned s = a[0] + a[1] + a[2] + a[3];
    unsigned v = s;
#pragma unroll
    for (int o = 1; o < 32; o <<= 1) { unsigned t = __shfl_up_sync(0xffffffffu, v, o); if (lane >= o) v += t; }
    if (lane == 31) ws[wid] = v;
    __syncthreads();
    if (wid == 0) {
        unsigned w = (lane < 16) ? ws[lane] : 0u;
#pragma unroll
        for (int o = 1; o < 32; o <<= 1) { unsigned t = __shfl_up_sync(0xffffffffu, w, o); if (lane >= o) w += t; }
        ws[lane] = w;
    }
    __syncthreads();
    unsigned warpoff = wid ? ws[wid - 1] : 0u;
    excl = warpoff + v - s;
    return ws[15];
}

__device__ __forceinline__ unsigned f2key(float v) {
    unsigned b = __float_as_uint(v);
    return (b & 0x80000000u) ? ~b : (b | 0x80000000u);
}
__device__ __forceinline__ float key2f(unsigned k) {
    unsigned b = (k & 0x80000000u) ? (k ^ 0x80000000u) : ~k;
    return __uint_as_float(b);
}

__device__ __forceinline__ unsigned long long pk2(float lo, float hi) {
    unsigned long long u;
    asm("mov.b64 %0,{%1,%2};" : "=l"(u) : "f"(lo), "f"(hi));
    return u;
}
__device__ __forceinline__ void upk2(unsigned long long u, float& lo, float& hi) {
    asm("mov.b64 {%0,%1},%2;" : "=f"(lo), "=f"(hi) : "l"(u));
}
__device__ __forceinline__ unsigned long long fma2(unsigned long long a,
                                                   unsigned long long b,
                                                   unsigned long long c) {
    unsigned long long d;
    asm("fma.rn.f32x2 %0,%1,%2,%3;" : "=l"(d) : "l"(a), "l"(b), "l"(c));
    return d;
}

__device__ void inv4(const float* m, float* inv) {
    float s0 = m[0] * m[5] - m[4] * m[1];
    float s1 = m[0] * m[6] - m[4] * m[2];
    float s2 = m[0] * m[7] - m[4] * m[3];
    float s3 = m[1] * m[6] - m[5] * m[2];
    float s4 = m[1] * m[7] - m[5] * m[3];
    float s5 = m[2] * m[7] - m[6] * m[3];
    float c5 = m[10] * m[15] - m[14] * m[11];
    float c4 = m[9] * m[15] - m[13] * m[11];
    float c3 = m[9] * m[14] - m[13] * m[10];
    float c2 = m[8] * m[15] - m[12] * m[11];
    float c1 = m[8] * m[14] - m[12] * m[10];
    float c0 = m[8] * m[13] - m[12] * m[9];
    float det = s0 * c5 - s1 * c4 + s2 * c3 + s3 * c2 - s4 * c1 + s5 * c0;
    float id = 1.f / det;
    inv[0]  = ( m[5] * c5 - m[6] * c4 + m[7] * c3) * id;
    inv[1]  = (-m[1] * c5 + m[2] * c4 - m[3] * c3) * id;
    inv[2]  = ( m[13] * s5 - m[14] * s4 + m[15] * s3) * id;
    inv[3]  = (-m[9] * s5 + m[10] * s4 - m[11] * s3) * id;
    inv[4]  = (-m[4] * c5 + m[6] * c2 - m[7] * c1) * id;
    inv[5]  = ( m[0] * c5 - m[2] * c2 + m[3] * c1) * id;
    inv[6]  = (-m[12] * s5 + m[14] * s2 - m[15] * s1) * id;
    inv[7]  = ( m[8] * s5 - m[10] * s2 + m[11] * s1) * id;
    inv[8]  = ( m[4] * c4 - m[5] * c2 + m[7] * c0) * id;
    inv[9]  = (-m[0] * c4 + m[1] * c2 - m[3] * c0) * id;
    inv[10] = ( m[12] * s4 - m[13] * s2 + m[15] * s0) * id;
    inv[11] = (-m[8] * s4 + m[9] * s2 - m[11] * s0) * id;
    inv[12] = (-m[4] * c3 + m[5] * c1 - m[6] * c0) * id;
    inv[13] = ( m[0] * c3 - m[1] * c1 + m[2] * c0) * id;
    inv[14] = (-m[12] * s3 + m[13] * s1 - m[14] * s0) * id;
    inv[15] = ( m[8] * s3 - m[9] * s1 + m[10] * s0) * id;
}

__device__ void mm4(const float* A, const float* B, float* C) {
    for (int i = 0; i < 4; i++)
        for (int j = 0; j < 4; j++) {
            float s = 0.f;
            for (int k = 0; k < 4; k++) s += A[i * 4 + k] * B[k * 4 + j];
            C[i * 4 + j] = s;
        }
}

// normal: cross(fy_diff, fx_diff) / max(||.||, 1e-6), via guarded rsqrt (1 MUFU)
__device__ __forceinline__ void compnorm(int x, int y,
                                         float dL, float dR, float dU, float dD,
                                         float cx, float cy, float ifx, float ify,
                                         float* out) {
    float Rx = ((float)(x + 1) - cx) * ifx * dR, Ry = ((float)y - cy) * ify * dR, Rz = dR;
    float Lx = ((float)(x - 1) - cx) * ifx * dL, Ly = ((float)y - cy) * ify * dL, Lz = dL;
    float Dx = ((float)x - cx) * ifx * dD, Dy = ((float)(y + 1) - cy) * ify * dD, Dz = dD;
    float Ux = ((float)x - cx) * ifx * dU, Uy = ((float)(y - 1) - cy) * ify * dU, Uz = dU;
    float bx = Rx - Lx, by = Ry - Ly, bz = Rz - Lz;
    float ax = Dx - Ux, ay = Dy - Uy, az = Dz - Uz;
    float c0 = ay * bz - az * by;
    float c1 = az * bx - ax * bz;
    float c2 = ax * by - ay * bx;
    float s = c0 * c0 + c1 * c1 + c2 * c2;
    // ||c|| >= 1e-6  <=>  s >= 1e-12 : use rsqrt; else divide by the 1e-6 floor.
    float iv = (s >= 1e-12f) ? rsqrtf(s) : 1e6f;
    out[0] = c0 * iv; out[1] = c1 * iv; out[2] = c2 * iv;
}

// ================= kernel A: selection pipeline + per-pixel losses + gather =================
// 296 blocks, 2/SM guaranteed by launch_bounds(512,2) -> all co-resident, gsync safe.
__global__ void __launch_bounds__(NTHR, 2) kA(
    const float* __restrict__ dp, const float* __restrict__ ppts,
    const float* __restrict__ dg, const float* __restrict__ intr,
    const float* __restrict__ posep, const float* __restrict__ poseg) {
    __shared__ unsigned sh[2048];
    __shared__ unsigned ws[32];
    __shared__ float shf[32];
    __shared__ unsigned s_p0[2], s_r1[2], s_p1[2], s_r2[2];
    __shared__ unsigned s_selbin, s_selneed, s_selT;
    __shared__ int s_low;
    __shared__ float s_sval[2], s_scale;

    const int bid = blockIdx.x, tix = threadIdx.x;
    const int f = bid & 3, cb = bid >> 2;   // cb in 0..73
    const float* dpf = dp + (size_t)f * HW;
    const float* dgf = dg + (size_t)f * HW;

    if (bid == NBLK - 1 && tix == 0) {
        float ip[16], ig[16];
        inv4(posep, ip);
        inv4(poseg, ig);
        float acc = 0.f;
        for (int s = 0; s < NF; s++) {
            float rp[16], rg[16];
            mm4(ip, posep + s * 16, rp);
            mm4(ig, poseg + s * 16, rg);
            for (int k = 0; k < 16; k++) acc += fabsf(rp[k] - rg[k]);
            g_relgt[s][0] = rg[0];  g_relgt[s][1] = rg[1];  g_relgt[s][2] = rg[2];
            g_relgt[s][3] = rg[4];  g_relgt[s][4] = rg[5];  g_relgt[s][5] = rg[6];
            g_relgt[s][6] = rg[8];  g_relgt[s][7] = rg[9];  g_relgt[s][8] = rg[10];
            g_relgt[s][9] = rg[3];  g_relgt[s][10] = rg[7]; g_relgt[s][11] = rg[11];
        }
        g_pose_loss = (double)(acc / 64.f);
    }

    // ---------- P1: keys, L0 hists, mask bits ----------
    for (int i = tix; i < 2048; i += NTHR) sh[i] = 0;
    __syncthreads();
    for (int pi = cb * NTHR + tix; pi < HW; pi += FSTRIDE) {
        float dgv = dgf[pi], dpv = dpf[pi];
        bool mk = isfinite(dgv) && (dgv > 1e-6f);
        bool mm = mk && isfinite(dpv) && (dpv > 1e-6f);
        unsigned key = 0u;
        if (mm) {
            float r = dpv / fmaxf(dgv, EPSF);
            key = f2key(r);
            if (!key) key = 1u;
        }
        g_medkeys[f * HW + pi] = key;
        if (key) atomicAdd(&sh[key >> 21], 1u);
        unsigned bal = __ballot_sync(0xffffffffu, mk);
        if ((pi & 31) == 0) g_maskbits[(f * HW + pi) >> 5] = bal;
        unsigned sk = (((unsigned)pi * 2654435761u) & 0xFFFFFu) | (mk ? (1u << 20) : 0u);
        atomicAdd(&g_sh0[f][sk >> 10], 1u);
    }
    __syncthreads();
    for (int i = tix; i < 2048; i += NTHR) {
        unsigned v = sh[i];
        if (v) atomicAdd(&g_h0[f][i], v);
    }
    gsync();

    // ---------- P2: local L0 scans + L1 hists ----------
    {
        if (tix == 0) { s_p0[0] = s_p0[1] = 0; s_r1[0] = s_r1[1] = 0; }
        unsigned a[4];
#pragma unroll
        for (int k = 0; k < 4; k++) a[k] = g_h0[f][4 * tix + k];
        unsigned excl;
        unsigned total = blockScan4(a, ws, excl);
        if (tix == 0) s_low = (total < 16) ? 1 : 0;
        if (total) {
            unsigned r0, r1;
            if (total & 1u) { r0 = total >> 1; r1 = r0; }
            else { r0 = (total >> 1) - 1u; r1 = total >> 1; }
            unsigned rks[2] = {r0, r1};
#pragma unroll
            for (int q = 0; q < 2; q++) {
                unsigned rk = rks[q], cum = excl;
#pragma unroll
                for (int k = 0; k < 4; k++) {
                    if (rk >= cum && rk < cum + a[k]) { s_p0[q] = 4 * tix + k; s_r1[q] = rk - cum; }
                    cum += a[k];
                }
            }
        }
        unsigned b4[4];
#pragma unroll
        for (int k = 0; k < 4; k++) b4[k] = g_sh0[f][4 * tix + k];
        unsigned excl2;
        unsigned tot2 = blockScan4(b4, ws, excl2);
        unsigned rk = tot2 - NSAMP, cum = excl2;
#pragma unroll
        for (int k = 0; k < 4; k++) {
            if (rk >= cum && rk < cum + b4[k]) { s_selbin = 4 * tix + k; s_selneed = cum + b4[k] - rk; }
            cum += b4[k];
        }
        __syncthreads();
        unsigned p0 = s_p0[0], p1 = s_p0[1], selbin = s_selbin;
        for (int pi = cb * NTHR + tix; pi < HW; pi += FSTRIDE) {
            unsigned key = g_medkeys[f * HW + pi];
            if (key) {
                unsigned top = key >> 21, mid = (key >> 10) & 2047u;
                if (top == p0) atomicAdd(&g_h1[f][0][mid], 1u);
                if (p1 != p0 && top == p1) atomicAdd(&g_h1[f][1][mid], 1u);
            }
            unsigned mk = (g_maskbits[(f * HW + pi) >> 5] >> (pi & 31)) & 1u;
            unsigned sk = (((unsigned)pi * 2654435761u) & 0xFFFFFu) | (mk << 20);
            if ((sk >> 10) == selbin) atomicAdd(&g_sh1[f][sk & 1023u], 1u);
        }
    }
    gsync();

    // ---------- P3: local L1 scans + L2 hist ----------
    {
        if (tix == 0) { s_p1[0] = s_p1[1] = 0; s_r2[0] = s_r2[1] = 0; }
        bool eq = (s_p0[0] == s_p0[1]);
#pragma unroll
        for (int q = 0; q < 2; q++) {
            int src = (eq && q == 1) ? 0 : q;
            unsigned a[4];
#pragma unroll
            for (int k = 0; k < 4; k++) a[k] = g_h1[f][src][4 * tix + k];
            unsigned excl;
            blockScan4(a, ws, excl);
            unsigned rk = s_r1[q], cum = excl;
#pragma unroll
            for (int k = 0; k < 4; k++) {
                if (rk >= cum && rk < cum + a[k]) {
                    s_p1[q] = (s_p0[q] << 11) | (unsigned)(4 * tix + k);
                    s_r2[q] = rk - cum;
                }
                cum += a[k];
            }
        }
        __syncthreads();
        unsigned q0 = s_p1[0], q1 = s_p1[1];
        for (int pi = cb * NTHR + tix; pi < HW; pi += FSTRIDE) {
            unsigned key = g_medkeys[f * HW + pi];
            if (!key) continue;
            unsigned hi = key >> 10;
            if (hi == q0) atomicAdd(&g_h2[f][0][key & 1023u], 1u);
            if (q1 != q0 && hi == q1) atomicAdd(&g_h2[f][1][key & 1023u], 1u);
        }
    }
    gsync();

    // ---------- P4: L2 scans -> scale; sel L1 scan -> selT; pixel+gather ----------
    {
        if (tix < 2) s_sval[tix] = 0.f;
        bool eq = (s_p1[0] == s_p1[1]);
#pragma unroll
        for (int q = 0; q < 2; q++) {
            int src = (eq && q == 1) ? 0 : q;
            unsigned a[4];
#pragma unroll
            for (int k = 0; k < 4; k++) a[k] = (4 * tix + k < 1024) ? g_h2[f][src][4 * tix + k] : 0u;
            unsigned excl;
            blockScan4(a, ws, excl);
            unsigned rk = s_r2[q], cum = excl;
#pragma unroll
            for (int k = 0; k < 4; k++) {
                if (4 * tix + k < 1024 && rk >= cum && rk < cum + a[k])
                    s_sval[q] = key2f((s_p1[q] << 10) | (unsigned)(4 * tix + k));
                cum += a[k];
            }
        }
        {
            unsigned a[4];
#pragma unroll
            for (int k = 0; k < 4; k++) a[k] = (4 * tix + k < 1024) ? g_sh1[f][4 * tix + k] : 0u;
            unsigned excl;
            unsigned tot = blockScan4(a, ws, excl);
            unsigned rk = tot - s_selneed, cum = excl;
#pragma unroll
            for (int k = 0; k < 4; k++) {
                if (4 * tix + k < 1024 && rk >= cum && rk < cum + a[k])
                    s_selT = (s_selbin << 10) | (unsigned)(4 * tix + k);
                cum += a[k];
            }
        }
        __syncthreads();
        if (tix == 0) {
            float med = 0.5f * (s_sval[0] + s_sval[1]);
            s_scale = (s_low || !isfinite(med)) ? 1.f : fminf(fmaxf(med, 1e-3f), 1e3f);
        }
        __syncthreads();

        const float sc = s_scale;
        const unsigned T = s_selT;
        const float fx = fmaxf(intr[f * 9 + 0], EPSF), fy = fmaxf(intr[f * 9 + 4], EPSF);
        const float cx = intr[f * 9 + 2], cy = intr[f * 9 + 5];
        const float ifx = 1.f / fx, ify = 1.f / fy;
        const float r00 = g_relgt[f][0], r01 = g_relgt[f][1], r02 = g_relgt[f][2];
        const float r10 = g_relgt[f][3], r11 = g_relgt[f][4], r12 = g_relgt[f][5];
        const float r20 = g_relgt[f][6], r21 = g_relgt[f][7], r22 = g_relgt[f][8];
        const float t0 = g_relgt[f][9], t1 = g_relgt[f][10], t2 = g_relgt[f][11];
        const int lane = tix & 31;

        float accm = 0.f, accl1 = 0.f, accn = 0.f;
        for (int pi = cb * NTHR + tix; pi < HW; pi += FSTRIDE) {
            int y = pi / W_, x = pi - y * W_;
            float dgv = dgf[pi], dpv = dpf[pi];
            bool mask = isfinite(dgv) && (dgv > 1e-6f);
            float mterm = mask ? 1.f : 0.f;
            accm += mterm;
            accl1 += fabsf(dpv - dgv * sc) * mterm;
            float cosv = 0.f;
            if (x > 0 && x < W_ - 1 && y > 0 && y < H_ - 1) {
                float pL = dpf[pi - 1], pR = dpf[pi + 1], pU = dpf[pi - W_], pD = dpf[pi + W_];
                float gL = dgf[pi - 1] * sc, gR = dgf[pi + 1] * sc, gU = dgf[pi - W_] * sc, gD = dgf[pi + W_] * sc;
                float n1[3], n2[3];
                compnorm(x, y, pL, pR, pU, pD, cx, cy, ifx, ify, n1);
                compnorm(x, y, gL, gR, gU, gD, cx, cy, ifx, ify, n2);
                float d = n1[0] * n2[0] + n1[1] * n2[1] + n1[2] * n2[2];
                cosv = fminf(fmaxf(d, -1.f), 1.f);
            }
            accn += (1.f - cosv) * mterm;

            unsigned sk = (((unsigned)pi * 2654435761u) & 0xFFFFFu) | (mask ? (1u << 20) : 0u);
            bool sel = (sk >= T);
            unsigned ball = __ballot_sync(0xffffffffu, sel);
            if (sel) {
                int leader = __ffs(ball) - 1;
                int base;
                if (lane == leader) base = atomicAdd(&g_selcount[f], __popc(ball));
                base = __shfl_sync(ball, base, leader);
                int slot = base + __popc(ball & ((1u << lane) - 1u));
                if (slot < NSAMP) {
                    float w = mask ? 1.f : 0.f;
                    const float* pp3 = ppts + ((size_t)f * HW + pi) * 3;
                    float px = pp3[0], py = pp3[1], pz = pp3[2];
                    if (!mask) { px = 1e9f; py = 1e9f; pz = 1e9f; }
                    g_ps[f][slot] = make_float4(px, py, pz, 0.5f * (px * px + py * py + pz * pz));
                    float dgal = dgv * sc;
                    float X = ((float)x - cx) * ifx * dgal;
                    float Y = ((float)y - cy) * ify * dgal;
                    float Z = dgal;
                    float gx = r00 * X + r01 * Y + r02 * Z + t0;
                    float gy = r10 * X + r11 * Y + r12 * Z + t1;
                    float gz = r20 * X + r21 * Y + r22 * Z + t2;
                    if (!mask) { gx = 1e9f; gy = 1e9f; gz = 1e9f; }
                    g_gs[f][slot] = make_float4(gx, gy, gz, 0.5f * (gx * gx + gy * gy + gz * gz));
                    g_w[f][slot] = w;
                }
            }
        }
        float s;
        s = blockReduceSum(accl1, shf);
        if (tix == 0) atomicAdd(&g_sum_absdiff, (double)s);
        __syncthreads();
        s = blockReduceSum(accn, shf);
        if (tix == 0) atomicAdd(&g_sum_normal, (double)s);
        __syncthreads();
        s = blockReduceSum(accm, shf);
        if (tix == 0 && s != 0.f) atomicAdd(&g_mask_frame[f], s);
    }
}

// ========== kernel B: chamfer, 256 blocks x 512 threads, 2 rows/thread, 512-col tile ==========
__global__ void __launch_bounds__(512, 2) kB() {
    __shared__ ulonglong2 sP[256];
    __shared__ ulonglong2 sQ[256];

    const int bid = blockIdx.x, tix = threadIdx.x;
    const int dir = bid & 1, f = (bid >> 1) & 3, rowblk = (bid >> 3) & 3, colblk = bid >> 5;
    const float4* A = dir ? g_gs[f] : g_ps[f];
    const float4* B = dir ? g_ps[f] : g_gs[f];

    const int cbase = colblk * 512;
    if (tix < 256) {
        float4 c0 = B[cbase + 2 * tix];
        float4 c1 = B[cbase + 2 * tix + 1];
        sP[tix] = make_ulonglong2(pk2(c0.x, c1.x), pk2(c0.y, c1.y));
        sQ[tix] = make_ulonglong2(pk2(c0.z, c1.z), pk2(c0.w, c1.w));
    }
    const int r0 = rowblk * 1024 + tix, r1 = r0 + 512;
    float4 a0 = A[r0], a1 = A[r1];
    unsigned long long nax0 = pk2(-a0.x, -a0.x), nay0 = pk2(-a0.y, -a0.y), naz0 = pk2(-a0.z, -a0.z);
    unsigned long long nax1 = pk2(-a1.x, -a1.x), nay1 = pk2(-a1.y, -a1.y), naz1 = pk2(-a1.z, -a1.z);
    float m0a = 3e38f, m0b = 3e38f, m1a = 3e38f, m1b = 3e38f;
    __syncthreads();
#pragma unroll 8
    for (int j = 0; j < 256; j++) {
        ulonglong2 va = sP[j], vb = sQ[j];
        unsigned long long u0 = fma2(nax0, va.x, vb.y);
        u0 = fma2(nay0, va.y, u0);
        u0 = fma2(naz0, vb.x, u0);
        unsigned long long u1 = fma2(nax1, va.x, vb.y);
        u1 = fma2(nay1, va.y, u1);
        u1 = fma2(naz1, vb.x, u1);
        float e0, e1;
        upk2(u0, e0, e1);
        m0a = fminf(m0a, e0); m0b = fminf(m0b, e1);
        upk2(u1, e0, e1);
        m1a = fminf(m1a, e0); m1b = fminf(m1b, e1);
    }
    atomicMax(&g_rowmax[dir][f][r0], ~f2key(fminf(m0a, m0b)));
    atomicMax(&g_rowmax[dir][f][r1], ~f2key(fminf(m1a, m1b)));
}

// ========== kernel C: per-(dir,frame) reduce + last-block combine + state reset ==========
__global__ void kC(float* out) {
    __shared__ float shf[32];
    __shared__ int s_last;
    const int b = blockIdx.x, tix = threadIdx.x;   // 8 blocks x 512
    const int f = b & 3, dir = b >> 2;
    float acc = 0.f, accw = 0.f;
    for (int i = tix; i < NSAMP; i += 512) {
        float rmin = key2f(~g_rowmax[dir][f][i]);
        float aw = dir ? g_gs[f][i].w : g_ps[f][i].w;
        float w = g_w[f][i];
        float d = fminf(sqrtf(fmaxf(2.f * (rmin + aw), 1e-12f)), 1e9f);
        acc += d * w;
        accw += w;
    }
    float r = blockReduceSum(acc, shf);
    if (tix == 0) g_cd[b] = r;
    __syncthreads();
    float rw = blockReduceSum(accw, shf);
    if (tix == 0 && dir == 0) g_wl[f] = rw;

    for (int i = tix; i < NSAMP; i += 512) g_rowmax[dir][f][i] = 0u;

    {
        const int gs = 8 * 512;
        int g = b * 512 + tix;
        unsigned* h0 = (unsigned*)g_h0;   for (int i = g; i < NF * 2048; i += gs) h0[i] = 0u;
        unsigned* s0 = (unsigned*)g_sh0;  for (int i = g; i < NF * 2048; i += gs) s0[i] = 0u;
        unsigned* h1 = (unsigned*)g_h1;   for (int i = g; i < NF * 2 * 2048; i += gs) h1[i] = 0u;
        unsigned* h2 = (unsigned*)g_h2;   for (int i = g; i < NF * 2 * 1024; i += gs) h2[i] = 0u;
        unsigned* s1 = (unsigned*)g_sh1;  for (int i = g; i < NF * 1024; i += gs) s1[i] = 0u;
    }

    __threadfence();
    __syncthreads();
    if (tix == 0) s_last = (atomicAdd(&g_done, 1u) == 7u) ? 1 : 0;
    __syncthreads();
    if (!s_last) return;

    if (tix == 0) {
        float wsum = g_mask_frame[0] + g_mask_frame[1] + g_mask_frame[2] + g_mask_frame[3];
        float denom = fmaxf(wsum, 1.f);
        float depth_loss = (float)g_sum_absdiff / denom;
        float normal_loss = (float)g_sum_normal / denom;
        float cds = 0.f, oks = 0.f;
        for (int ff = 0; ff < NF; ff++) {
            float dn = fmaxf(g_wl[ff], 1.f);
            if (g_mask_frame[ff] >= 10.f) { cds += (g_cd[ff] + g_cd[4 + ff]) / dn; oks += 1.f; }
        }
        float points_loss = cds / fmaxf(oks, 1.f);
        out[0] = (float)g_pose_loss + depth_loss + points_loss + normal_loss;
    }
    __syncthreads();
    if (tix < NF) { g_mask_frame[tix] = 0.f; g_selcount[tix] = 0; }
    if (tix == NF) { g_sum_absdiff = 0.0; g_sum_normal = 0.0; g_done = 0u; }
}

// ---------------- launcher ----------------
extern "C" void kernel_launch(void* const* d_in, const int* in_sizes, int n_in,
                              void* d_out, int out_size) {
    const float* depth_pred = (const float*)d_in[0];
    const float* points_pred = (const float*)d_in[1];
    const float* depth_gt = (const float*)d_in[2];
    const float* intrinsics = (const float*)d_in[3];
    const float* pose_pred = (const float*)d_in[4];
    const float* pose_gt = (const float*)d_in[5];
    float* out = (float*)d_out;

    kA<<<NBLK, NTHR>>>(depth_pred, points_pred, depth_gt, intrinsics, pose_pred, pose_gt);
    kB<<<256, 512>>>();
    kC<<<8, 512>>>(out);
}